// round 1
// baseline (speedup 1.0000x reference)
#include <cuda_runtime.h>
#include <math.h>

#define DM 1024
#define NH 16
#define DK 64
#define SEQ 2048
#define NTOK 4096   // B * SEQ

// ---------------- scratch (device globals: no allocations allowed) ----------------
__device__ float g_WQP[DM * DM];
__device__ float g_WKP[DM * DM];
__device__ float g_BQP[DM];
__device__ float g_BKP[DM];
__device__ float g_QF[NTOK * DM];
__device__ float g_KF[NTOK * DM];
__device__ float g_VP[NTOK * DM];
__device__ float g_CTX[NTOK * DM];

// ---------------- fold per-head feature-map weights into projection ----------------
// wout[:, h*64+j] = w[:, h*64 + :] @ wn[:, j];  bout = (b_head @ wn) + bn
__global__ void fold_weights(const float* __restrict__ w, const float* __restrict__ b,
                             const float* __restrict__ wn, const float* __restrict__ bn,
                             float* __restrict__ wout, float* __restrict__ bout) {
    int idx = blockIdx.x * blockDim.x + threadIdx.x;
    if (idx >= DM * DM) return;
    int i = idx >> 10;       // input dim
    int j = idx & 1023;      // output dim
    int h = j >> 6, jj = j & 63;
    const float* wrow = w + i * DM + h * DK;
    float acc = 0.f;
#pragma unroll 8
    for (int d = 0; d < DK; d++) acc += wrow[d] * wn[d * DK + jj];
    wout[idx] = acc;
    if (i == 0) {
        float bb = bn[jj];
        for (int d = 0; d < DK; d++) bb += b[h * DK + d] * wn[d * DK + jj];
        bout[j] = bb;
    }
}

// ---------------- tiled fp32 GEMM: C[M,1024] = act(A[M,1024] @ W[1024,1024] + bias) --
__global__ void __launch_bounds__(256) gemm_bias_act(
    const float* __restrict__ A, const float* __restrict__ W,
    const float* __restrict__ bias, float* __restrict__ C, int act) {
    __shared__ float As[16][64];
    __shared__ float Bs[16][64];
    int tid = threadIdx.x;
    int tx = tid & 15, ty = tid >> 4;
    int bm = blockIdx.y * 64, bn = blockIdx.x * 64;

    float acc[4][4] = {};
    int arow = tid >> 2, acol = (tid & 3) << 2;   // A tile 64x16
    int brow = tid >> 4, bcol = (tid & 15) << 2;  // B tile 16x64
    const float* Aptr = A + (size_t)(bm + arow) * DM + acol;
    const float* Wptr = W + (size_t)brow * DM + bn + bcol;

    for (int k0 = 0; k0 < DM; k0 += 16) {
        float4 av = *(const float4*)(Aptr + k0);
        As[acol + 0][arow] = av.x;
        As[acol + 1][arow] = av.y;
        As[acol + 2][arow] = av.z;
        As[acol + 3][arow] = av.w;
        *(float4*)&Bs[brow][bcol] = *(const float4*)(Wptr + (size_t)k0 * DM);
        __syncthreads();
#pragma unroll
        for (int kk = 0; kk < 16; kk++) {
            float4 a = *(const float4*)&As[kk][ty << 2];
            float4 w4 = *(const float4*)&Bs[kk][tx << 2];
            acc[0][0] += a.x * w4.x; acc[0][1] += a.x * w4.y; acc[0][2] += a.x * w4.z; acc[0][3] += a.x * w4.w;
            acc[1][0] += a.y * w4.x; acc[1][1] += a.y * w4.y; acc[1][2] += a.y * w4.z; acc[1][3] += a.y * w4.w;
            acc[2][0] += a.z * w4.x; acc[2][1] += a.z * w4.y; acc[2][2] += a.z * w4.z; acc[2][3] += a.z * w4.w;
            acc[3][0] += a.w * w4.x; acc[3][1] += a.w * w4.y; acc[3][2] += a.w * w4.z; acc[3][3] += a.w * w4.w;
        }
        __syncthreads();
    }
    float4 bi = *(const float4*)&bias[bn + (tx << 2)];
#pragma unroll
    for (int i = 0; i < 4; i++) {
        int m = bm + (ty << 2) + i;
        float4 o;
        o.x = acc[i][0] + bi.x; o.y = acc[i][1] + bi.y;
        o.z = acc[i][2] + bi.z; o.w = acc[i][3] + bi.w;
        if (act) { o.x = tanhf(o.x); o.y = tanhf(o.y); o.z = tanhf(o.z); o.w = tanhf(o.w); }
        *(float4*)&C[(size_t)m * DM + bn + (tx << 2)] = o;
    }
}

// ---------------- flash attention (fp32, 64x64 tiles, online softmax) ---------------
// smem carve: Qs[64d][68] transposed, Ks[64d][68] transposed, Vs[64k][64d], Ps[64q][65k]
#define FLASH_SMEM ((64 * 68 * 2 + 64 * 64 + 64 * 65) * 4)

__global__ void __launch_bounds__(256) flash_attn(
    const float* __restrict__ QF, const float* __restrict__ KF,
    const float* __restrict__ V, const int* __restrict__ mask,
    const float* __restrict__ temp, float* __restrict__ CTX) {
    extern __shared__ float sm[];
    float* Qs = sm;                 // [d*68 + q]
    float* Ks = sm + 64 * 68;       // [d*68 + k]
    float* Vs = Ks + 64 * 68;       // [k*64 + d]
    float* Ps = Vs + 64 * 64;       // [q*65 + k]

    int qt = blockIdx.x, h = blockIdx.y, b = blockIdx.z;
    int tid = threadIdx.x;
    int tx = tid & 15, ty = tid >> 4;
    int q0 = qt * 64;

    // load Q tile transposed
    {
        int r = tid >> 2, c0 = (tid & 3) << 4;
        const float* src = QF + (size_t)(b * SEQ + q0 + r) * DM + h * DK + c0;
#pragma unroll
        for (int c = 0; c < 4; c++) {
            float4 v4 = *(const float4*)(src + c * 4);
            int d = c0 + c * 4;
            Qs[(d + 0) * 68 + r] = v4.x;
            Qs[(d + 1) * 68 + r] = v4.y;
            Qs[(d + 2) * 68 + r] = v4.z;
            Qs[(d + 3) * 68 + r] = v4.w;
        }
    }
    float scale = 0.125f / temp[h];

    float m_i[4], l_i[4], acc[4][4];
#pragma unroll
    for (int i = 0; i < 4; i++) {
        m_i[i] = -1e30f; l_i[i] = 0.f;
#pragma unroll
        for (int j = 0; j < 4; j++) acc[i][j] = 0.f;
    }

    for (int kt = 0; kt < SEQ / 64; kt++) {
        __syncthreads();   // protect Ks/Vs reuse
        {
            int r = tid >> 2, c0 = (tid & 3) << 4;
            const float* ksrc = KF + (size_t)(b * SEQ + kt * 64 + r) * DM + h * DK + c0;
            const float* vsrc = V + (size_t)(b * SEQ + kt * 64 + r) * DM + h * DK + c0;
#pragma unroll
            for (int c = 0; c < 4; c++) {
                int d = c0 + c * 4;
                float4 kv = *(const float4*)(ksrc + c * 4);
                Ks[(d + 0) * 68 + r] = kv.x;
                Ks[(d + 1) * 68 + r] = kv.y;
                Ks[(d + 2) * 68 + r] = kv.z;
                Ks[(d + 3) * 68 + r] = kv.w;
                *(float4*)&Vs[r * 64 + d] = *(const float4*)(vsrc + c * 4);
            }
        }
        __syncthreads();

        // S = Qf @ Kf^T  (64x64x64)
        float s[4][4] = {};
#pragma unroll 16
        for (int d = 0; d < 64; d++) {
            float4 a = *(const float4*)&Qs[d * 68 + (ty << 2)];
            float4 k4 = *(const float4*)&Ks[d * 68 + (tx << 2)];
            s[0][0] += a.x * k4.x; s[0][1] += a.x * k4.y; s[0][2] += a.x * k4.z; s[0][3] += a.x * k4.w;
            s[1][0] += a.y * k4.x; s[1][1] += a.y * k4.y; s[1][2] += a.y * k4.z; s[1][3] += a.y * k4.w;
            s[2][0] += a.z * k4.x; s[2][1] += a.z * k4.y; s[2][2] += a.z * k4.z; s[2][3] += a.z * k4.w;
            s[3][0] += a.w * k4.x; s[3][1] += a.w * k4.y; s[3][2] += a.w * k4.z; s[3][3] += a.w * k4.w;
        }

        // scale + mask (mask is L2-resident, reused 32x)
        const int* mbase = mask + (size_t)(q0 + (ty << 2)) * SEQ + kt * 64 + (tx << 2);
#pragma unroll
        for (int i = 0; i < 4; i++) {
            int4 mr = *(const int4*)(mbase + (size_t)i * SEQ);
            s[i][0] = mr.x ? s[i][0] * scale : -1e9f;
            s[i][1] = mr.y ? s[i][1] * scale : -1e9f;
            s[i][2] = mr.z ? s[i][2] * scale : -1e9f;
            s[i][3] = mr.w ? s[i][3] * scale : -1e9f;
        }

        // online softmax per q-row (row owned by the 16 same-ty lanes)
#pragma unroll
        for (int i = 0; i < 4; i++) {
            float lm = fmaxf(fmaxf(s[i][0], s[i][1]), fmaxf(s[i][2], s[i][3]));
#pragma unroll
            for (int o = 8; o > 0; o >>= 1)
                lm = fmaxf(lm, __shfl_xor_sync(0xffffffffu, lm, o));
            float mnew = fmaxf(m_i[i], lm);
            float corr = __expf(m_i[i] - mnew);
            m_i[i] = mnew;
            float ls = 0.f;
#pragma unroll
            for (int j = 0; j < 4; j++) {
                s[i][j] = __expf(s[i][j] - mnew);
                ls += s[i][j];
            }
#pragma unroll
            for (int o = 8; o > 0; o >>= 1)
                ls += __shfl_xor_sync(0xffffffffu, ls, o);
            l_i[i] = l_i[i] * corr + ls;
            float* prow = &Ps[((ty << 2) + i) * 65 + (tx << 2)];
            prow[0] = s[i][0]; prow[1] = s[i][1]; prow[2] = s[i][2]; prow[3] = s[i][3];
#pragma unroll
            for (int j = 0; j < 4; j++) acc[i][j] *= corr;
        }
        __syncwarp();   // Ps rows are produced & consumed within the same warp

        // ctx += P @ V  (64x64x64)
#pragma unroll 16
        for (int k = 0; k < 64; k++) {
            float4 v4 = *(const float4*)&Vs[k * 64 + (tx << 2)];
            float p0 = Ps[((ty << 2) + 0) * 65 + k];
            float p1 = Ps[((ty << 2) + 1) * 65 + k];
            float p2 = Ps[((ty << 2) + 2) * 65 + k];
            float p3 = Ps[((ty << 2) + 3) * 65 + k];
            acc[0][0] += p0 * v4.x; acc[0][1] += p0 * v4.y; acc[0][2] += p0 * v4.z; acc[0][3] += p0 * v4.w;
            acc[1][0] += p1 * v4.x; acc[1][1] += p1 * v4.y; acc[1][2] += p1 * v4.z; acc[1][3] += p1 * v4.w;
            acc[2][0] += p2 * v4.x; acc[2][1] += p2 * v4.y; acc[2][2] += p2 * v4.z; acc[2][3] += p2 * v4.w;
            acc[3][0] += p3 * v4.x; acc[3][1] += p3 * v4.y; acc[3][2] += p3 * v4.z; acc[3][3] += p3 * v4.w;
        }
    }

    // epilogue: normalize and write ctx in merged-head layout [B,S,H*dk]
#pragma unroll
    for (int i = 0; i < 4; i++) {
        float inv = 1.0f / l_i[i];
        float4 o;
        o.x = acc[i][0] * inv; o.y = acc[i][1] * inv;
        o.z = acc[i][2] * inv; o.w = acc[i][3] * inv;
        *(float4*)&CTX[(size_t)(b * SEQ + q0 + (ty << 2) + i) * DM + h * DK + (tx << 2)] = o;
    }
}

// ---------------- in-place RMSNorm over last dim (1024) -----------------------------
__global__ void __launch_bounds__(256) rmsnorm_kernel(float* __restrict__ out,
                                                      const float* __restrict__ gamma) {
    int row = blockIdx.x;
    int tid = threadIdx.x;
    float4 x = *(const float4*)&out[(size_t)row * DM + (tid << 2)];
    float ss = x.x * x.x + x.y * x.y + x.z * x.z + x.w * x.w;
    __shared__ float red[8];
#pragma unroll
    for (int o = 16; o > 0; o >>= 1) ss += __shfl_xor_sync(0xffffffffu, ss, o);
    if ((tid & 31) == 0) red[tid >> 5] = ss;
    __syncthreads();
    if (tid < 8) {
        float sv = red[tid];
#pragma unroll
        for (int o = 4; o > 0; o >>= 1) sv += __shfl_xor_sync(0xffu, sv, o);
        if (tid == 0) red[0] = sv;
    }
    __syncthreads();
    float rms = rsqrtf(red[0] * (1.0f / (float)DM) + 1e-6f);
    float4 g = *(const float4*)&gamma[tid << 2];
    x.x *= rms * g.x; x.y *= rms * g.y; x.z *= rms * g.z; x.w *= rms * g.w;
    *(float4*)&out[(size_t)row * DM + (tid << 2)] = x;
}

// ---------------- launch -----------------------------------------------------------
extern "C" void kernel_launch(void* const* d_in, const int* in_sizes, int n_in,
                              void* d_out, int out_size) {
    (void)in_sizes; (void)n_in; (void)out_size;
    const float* Q    = (const float*)d_in[0];
    const float* K    = (const float*)d_in[1];
    const float* V    = (const float*)d_in[2];
    const int*   mask = (const int*)d_in[3];
    const float* wq   = (const float*)d_in[4];
    const float* bq   = (const float*)d_in[5];
    const float* wk   = (const float*)d_in[6];
    const float* bk   = (const float*)d_in[7];
    const float* wv   = (const float*)d_in[8];
    const float* bv   = (const float*)d_in[9];
    const float* wo   = (const float*)d_in[10];
    const float* bo   = (const float*)d_in[11];
    const float* wnq  = (const float*)d_in[12];
    const float* bnq  = (const float*)d_in[13];
    const float* wnk  = (const float*)d_in[14];
    const float* bnk  = (const float*)d_in[15];
    const float* temp = (const float*)d_in[16];
    const float* gamma= (const float*)d_in[17];
    float* out = (float*)d_out;

    float *WQP, *WKP, *BQP, *BKP, *QFp, *KFp, *VPp, *CTXp;
    cudaGetSymbolAddress((void**)&WQP, g_WQP);
    cudaGetSymbolAddress((void**)&WKP, g_WKP);
    cudaGetSymbolAddress((void**)&BQP, g_BQP);
    cudaGetSymbolAddress((void**)&BKP, g_BKP);
    cudaGetSymbolAddress((void**)&QFp, g_QF);
    cudaGetSymbolAddress((void**)&KFp, g_KF);
    cudaGetSymbolAddress((void**)&VPp, g_VP);
    cudaGetSymbolAddress((void**)&CTXp, g_CTX);

    cudaFuncSetAttribute(flash_attn, cudaFuncAttributeMaxDynamicSharedMemorySize, FLASH_SMEM);

    fold_weights<<<DM * DM / 256, 256>>>(wq, bq, wnq, bnq, WQP, BQP);
    fold_weights<<<DM * DM / 256, 256>>>(wk, bk, wnk, bnk, WKP, BKP);

    dim3 ggrid(DM / 64, NTOK / 64);
    gemm_bias_act<<<ggrid, 256>>>(Q, WQP, BQP, QFp, 1);
    gemm_bias_act<<<ggrid, 256>>>(K, WKP, BKP, KFp, 1);
    gemm_bias_act<<<ggrid, 256>>>(V, wv, bv, VPp, 0);

    dim3 agrid(SEQ / 64, NH, 2);
    flash_attn<<<agrid, 256, FLASH_SMEM>>>(QFp, KFp, VPp, mask, temp, CTXp);

    gemm_bias_act<<<ggrid, 256>>>(CTXp, wo, bo, out, 0);
    rmsnorm_kernel<<<NTOK, 256>>>(out, gamma);
}

// round 2
// speedup vs baseline: 2.0399x; 2.0399x over previous
#include <cuda_runtime.h>
#include <math.h>

#define DM 1024
#define NH 16
#define DK 64
#define SEQ 2048
#define NTOK 4096   // B * SEQ

// ---------------- scratch (device globals) ----------------
__device__ float g_WQP[DM * DM];
__device__ float g_WKP[DM * DM];
__device__ float g_BQP[DM];
__device__ float g_BKP[DM];
__device__ float g_QF[NTOK * DM];
__device__ float g_KF[NTOK * DM];
__device__ float g_VP[NTOK * DM];
__device__ float g_CTX[NTOK * DM];

// ---------------- helpers ----------------
__device__ __forceinline__ float rna_tf32(float x) {
    unsigned u;
    asm("cvt.rna.tf32.f32 %0, %1;" : "=r"(u) : "f"(x));
    return __uint_as_float(u);
}

__device__ __forceinline__ void mma8(float* c, const unsigned* a, unsigned b0, unsigned b1) {
    asm volatile(
        "mma.sync.aligned.m16n8k8.row.col.f32.tf32.tf32.f32 "
        "{%0,%1,%2,%3},{%4,%5,%6,%7},{%8,%9},{%0,%1,%2,%3};"
        : "+f"(c[0]), "+f"(c[1]), "+f"(c[2]), "+f"(c[3])
        : "r"(a[0]), "r"(a[1]), "r"(a[2]), "r"(a[3]), "r"(b0), "r"(b1));
}

// ---------------- fold per-head feature-map weights into projection ----------------
__global__ void fold_weights(const float* __restrict__ w, const float* __restrict__ b,
                             const float* __restrict__ wn, const float* __restrict__ bn,
                             float* __restrict__ wout, float* __restrict__ bout) {
    int idx = blockIdx.x * blockDim.x + threadIdx.x;
    if (idx >= DM * DM) return;
    int i = idx >> 10;
    int j = idx & 1023;
    int h = j >> 6, jj = j & 63;
    const float* wrow = w + i * DM + h * DK;
    float acc = 0.f;
#pragma unroll 8
    for (int d = 0; d < DK; d++) acc += wrow[d] * wn[d * DK + jj];
    wout[idx] = acc;
    if (i == 0) {
        float bb = bn[jj];
        for (int d = 0; d < DK; d++) bb += b[h * DK + d] * wn[d * DK + jj];
        bout[j] = bb;
    }
}

// ---------------- tf32 tensor-core GEMM: C[M,1024] = act(A @ W + bias) ----------------
// BM=128 BN=128 BK=32; 256 thr = 8 warps (2x4); warp tile 64x32; m16n8k8 frags.
#define GBM 128
#define GBN 128
#define GBK 32
#define GAS 136   // BM + 8 pad (stride%32 == 8 -> conflict-free frag loads)

__global__ void __launch_bounds__(256) gemm_tc(
    const float* __restrict__ A, const float* __restrict__ W,
    const float* __restrict__ bias, float* __restrict__ C, int act) {
    __shared__ __align__(16) float As[GBK][GAS];   // [k][m]
    __shared__ __align__(16) float Bs[GBK][GAS];   // [k][n]
    int tid = threadIdx.x;
    int warp = tid >> 5, lane = tid & 31;
    int g = lane >> 2, tig = lane & 3;
    int wm = warp >> 2, wn = warp & 3;
    int bm = blockIdx.y * GBM, bn = blockIdx.x * GBN;

    float acc[4][4][4];
#pragma unroll
    for (int m = 0; m < 4; m++)
#pragma unroll
        for (int j = 0; j < 4; j++)
#pragma unroll
            for (int t = 0; t < 4; t++) acc[m][j][t] = 0.f;

    for (int k0 = 0; k0 < DM; k0 += GBK) {
#pragma unroll
        for (int i = 0; i < 4; i++) {
            int idx = tid + 256 * i;
            {   // A tile 128x32 -> As[k][m]
                int r = idx >> 3, kk = (idx & 7) << 2;
                float4 v = *(const float4*)&A[(size_t)(bm + r) * DM + k0 + kk];
                As[kk + 0][r] = rna_tf32(v.x);
                As[kk + 1][r] = rna_tf32(v.y);
                As[kk + 2][r] = rna_tf32(v.z);
                As[kk + 3][r] = rna_tf32(v.w);
            }
            {   // W tile 32x128 -> Bs[k][n]
                int kk = idx >> 5, n4 = (idx & 31) << 2;
                float4 v = *(const float4*)&W[(size_t)(k0 + kk) * DM + bn + n4];
                v.x = rna_tf32(v.x); v.y = rna_tf32(v.y);
                v.z = rna_tf32(v.z); v.w = rna_tf32(v.w);
                *(float4*)&Bs[kk][n4] = v;
            }
        }
        __syncthreads();
#pragma unroll
        for (int s = 0; s < 4; s++) {
            unsigned a[4][4], bb[4][2];
#pragma unroll
            for (int m = 0; m < 4; m++) {
                int m0 = wm * 64 + m * 16;
                a[m][0] = __float_as_uint(As[8 * s + tig][m0 + g]);
                a[m][1] = __float_as_uint(As[8 * s + tig][m0 + g + 8]);
                a[m][2] = __float_as_uint(As[8 * s + tig + 4][m0 + g]);
                a[m][3] = __float_as_uint(As[8 * s + tig + 4][m0 + g + 8]);
            }
#pragma unroll
            for (int j = 0; j < 4; j++) {
                int n0 = wn * 32 + j * 8;
                bb[j][0] = __float_as_uint(Bs[8 * s + tig][n0 + g]);
                bb[j][1] = __float_as_uint(Bs[8 * s + tig + 4][n0 + g]);
            }
#pragma unroll
            for (int m = 0; m < 4; m++)
#pragma unroll
                for (int j = 0; j < 4; j++)
                    mma8(acc[m][j], a[m], bb[j][0], bb[j][1]);
        }
        __syncthreads();
    }

    // epilogue
#pragma unroll
    for (int m = 0; m < 4; m++) {
        int row0 = bm + wm * 64 + m * 16 + g;
#pragma unroll
        for (int j = 0; j < 4; j++) {
            int col = bn + wn * 32 + j * 8 + 2 * tig;
            float b0 = bias[col], b1 = bias[col + 1];
            float v0 = acc[m][j][0] + b0, v1 = acc[m][j][1] + b1;
            float v2 = acc[m][j][2] + b0, v3 = acc[m][j][3] + b1;
            if (act == 1) {
                v0 = rna_tf32(tanhf(v0)); v1 = rna_tf32(tanhf(v1));
                v2 = rna_tf32(tanhf(v2)); v3 = rna_tf32(tanhf(v3));
            } else if (act == 2) {
                v0 = rna_tf32(v0); v1 = rna_tf32(v1);
                v2 = rna_tf32(v2); v3 = rna_tf32(v3);
            }
            *(float2*)&C[(size_t)row0 * DM + col] = make_float2(v0, v1);
            *(float2*)&C[(size_t)(row0 + 8) * DM + col] = make_float2(v2, v3);
        }
    }
}

// ---------------- tensor-core flash attention ----------------
// 128 threads (4 warps), q-tile 64 (16 rows/warp), k-tile 64, tf32 mma.
// smem: Qs[64][68] (aliased by Ps after frag load), Ks[64][68], Vs[64][72]
#define FQS 68
#define FVS 72
#define FLASH_SMEM ((64 * FQS * 2 + 64 * FVS) * 4)

__global__ void __launch_bounds__(128) flash_tc(
    const float* __restrict__ QF, const float* __restrict__ KF,
    const float* __restrict__ V, const int* __restrict__ mask,
    const float* __restrict__ temp, float* __restrict__ CTX) {
    extern __shared__ __align__(16) float sm[];
    float* Qs = sm;                 // 64 x FQS  (later: Ps)
    float* Ks = sm + 64 * FQS;      // 64 x FQS
    float* Vs = Ks + 64 * FQS;      // 64 x FVS
    float* Ps = Qs;

    int tid = threadIdx.x;
    int warp = tid >> 5, lane = tid & 31;
    int g = lane >> 2, tig = lane & 3;
    int q0 = blockIdx.x * 64, h = blockIdx.y, b = blockIdx.z;
    int r0 = warp * 16 + g;

    // load Q tile (already tf32-rounded at GEMM epilogue)
#pragma unroll
    for (int i = 0; i < 8; i++) {
        int idx = tid + 128 * i;
        int r = idx >> 4, d4 = (idx & 15) << 2;
        *(float4*)&Qs[r * FQS + d4] =
            *(const float4*)&QF[(size_t)(b * SEQ + q0 + r) * DM + h * DK + d4];
    }
    __syncthreads();

    // Q fragments register-resident for the whole K loop
    unsigned qa[8][4];
#pragma unroll
    for (int s = 0; s < 8; s++) {
        qa[s][0] = __float_as_uint(Qs[r0 * FQS + 8 * s + tig]);
        qa[s][1] = __float_as_uint(Qs[(r0 + 8) * FQS + 8 * s + tig]);
        qa[s][2] = __float_as_uint(Qs[r0 * FQS + 8 * s + tig + 4]);
        qa[s][3] = __float_as_uint(Qs[(r0 + 8) * FQS + 8 * s + tig + 4]);
    }

    float scale = 0.125f / temp[h];
    float mr0 = -1e30f, mr1 = -1e30f, l0 = 0.f, l1 = 0.f;
    float acc[8][4];
#pragma unroll
    for (int j = 0; j < 8; j++)
#pragma unroll
        for (int t = 0; t < 4; t++) acc[j][t] = 0.f;

    for (int kt = 0; kt < SEQ / 64; kt++) {
        __syncthreads();   // protects Ps (=Qs) reads / Ks,Vs from previous iter
#pragma unroll
        for (int i = 0; i < 8; i++) {
            int idx = tid + 128 * i;
            int r = idx >> 4, d4 = (idx & 15) << 2;
            size_t src = (size_t)(b * SEQ + kt * 64 + r) * DM + h * DK + d4;
            *(float4*)&Ks[r * FQS + d4] = *(const float4*)&KF[src];
            *(float4*)&Vs[r * FVS + d4] = *(const float4*)&V[src];
        }
        __syncthreads();

        // S = Qf @ Kf^T  (64x64 over d=64)
        float sD[8][4];
#pragma unroll
        for (int j = 0; j < 8; j++)
#pragma unroll
            for (int t = 0; t < 4; t++) sD[j][t] = 0.f;
#pragma unroll
        for (int s = 0; s < 8; s++)
#pragma unroll
            for (int j = 0; j < 8; j++) {
                unsigned b0 = __float_as_uint(Ks[(8 * j + g) * FQS + 8 * s + tig]);
                unsigned b1 = __float_as_uint(Ks[(8 * j + g) * FQS + 8 * s + tig + 4]);
                mma8(sD[j], qa[s], b0, b1);
            }

        // scale + mask
#pragma unroll
        for (int j = 0; j < 8; j++) {
            int c = kt * 64 + 8 * j + 2 * tig;
            int2 mA = *(const int2*)&mask[(size_t)(q0 + r0) * SEQ + c];
            int2 mB = *(const int2*)&mask[(size_t)(q0 + r0 + 8) * SEQ + c];
            sD[j][0] = mA.x ? sD[j][0] * scale : -1e9f;
            sD[j][1] = mA.y ? sD[j][1] * scale : -1e9f;
            sD[j][2] = mB.x ? sD[j][2] * scale : -1e9f;
            sD[j][3] = mB.y ? sD[j][3] * scale : -1e9f;
        }

        // online softmax: row g (sD[j][0,1]) and row g+8 (sD[j][2,3]); quad = same g
        float mx0 = -1e30f, mx1 = -1e30f;
#pragma unroll
        for (int j = 0; j < 8; j++) {
            mx0 = fmaxf(mx0, fmaxf(sD[j][0], sD[j][1]));
            mx1 = fmaxf(mx1, fmaxf(sD[j][2], sD[j][3]));
        }
        mx0 = fmaxf(mx0, __shfl_xor_sync(0xffffffffu, mx0, 1));
        mx0 = fmaxf(mx0, __shfl_xor_sync(0xffffffffu, mx0, 2));
        mx1 = fmaxf(mx1, __shfl_xor_sync(0xffffffffu, mx1, 1));
        mx1 = fmaxf(mx1, __shfl_xor_sync(0xffffffffu, mx1, 2));
        float nm0 = fmaxf(mr0, mx0), nm1 = fmaxf(mr1, mx1);
        float corr0 = __expf(mr0 - nm0), corr1 = __expf(mr1 - nm1);
        mr0 = nm0; mr1 = nm1;

        float s0 = 0.f, s1 = 0.f;
#pragma unroll
        for (int j = 0; j < 8; j++) {
            float p0 = __expf(sD[j][0] - nm0);
            float p1 = __expf(sD[j][1] - nm0);
            float p2 = __expf(sD[j][2] - nm1);
            float p3 = __expf(sD[j][3] - nm1);
            s0 += p0 + p1; s1 += p2 + p3;
            *(float2*)&Ps[r0 * FQS + 8 * j + 2 * tig] =
                make_float2(rna_tf32(p0), rna_tf32(p1));
            *(float2*)&Ps[(r0 + 8) * FQS + 8 * j + 2 * tig] =
                make_float2(rna_tf32(p2), rna_tf32(p3));
        }
        s0 += __shfl_xor_sync(0xffffffffu, s0, 1);
        s0 += __shfl_xor_sync(0xffffffffu, s0, 2);
        s1 += __shfl_xor_sync(0xffffffffu, s1, 1);
        s1 += __shfl_xor_sync(0xffffffffu, s1, 2);
        l0 = l0 * corr0 + s0;
        l1 = l1 * corr1 + s1;
#pragma unroll
        for (int j = 0; j < 8; j++) {
            acc[j][0] *= corr0; acc[j][1] *= corr0;
            acc[j][2] *= corr1; acc[j][3] *= corr1;
        }
        __syncwarp();   // Ps rows produced & consumed by same warp

        // ctx += P @ V
#pragma unroll
        for (int s = 0; s < 8; s++) {
            unsigned pa[4];
            pa[0] = __float_as_uint(Ps[r0 * FQS + 8 * s + tig]);
            pa[1] = __float_as_uint(Ps[(r0 + 8) * FQS + 8 * s + tig]);
            pa[2] = __float_as_uint(Ps[r0 * FQS + 8 * s + tig + 4]);
            pa[3] = __float_as_uint(Ps[(r0 + 8) * FQS + 8 * s + tig + 4]);
#pragma unroll
            for (int j = 0; j < 8; j++) {
                unsigned b0 = __float_as_uint(Vs[(8 * s + tig) * FVS + 8 * j + g]);
                unsigned b1 = __float_as_uint(Vs[(8 * s + tig + 4) * FVS + 8 * j + g]);
                mma8(acc[j], pa, b0, b1);
            }
        }
    }

    // epilogue
    float inv0 = 1.0f / l0, inv1 = 1.0f / l1;
#pragma unroll
    for (int j = 0; j < 8; j++) {
        int col = h * DK + 8 * j + 2 * tig;
        *(float2*)&CTX[(size_t)(b * SEQ + q0 + r0) * DM + col] =
            make_float2(acc[j][0] * inv0, acc[j][1] * inv0);
        *(float2*)&CTX[(size_t)(b * SEQ + q0 + r0 + 8) * DM + col] =
            make_float2(acc[j][2] * inv1, acc[j][3] * inv1);
    }
}

// ---------------- in-place RMSNorm ----------------
__global__ void __launch_bounds__(256) rmsnorm_kernel(float* __restrict__ out,
                                                      const float* __restrict__ gamma) {
    int row = blockIdx.x;
    int tid = threadIdx.x;
    float4 x = *(const float4*)&out[(size_t)row * DM + (tid << 2)];
    float ss = x.x * x.x + x.y * x.y + x.z * x.z + x.w * x.w;
    __shared__ float red[8];
#pragma unroll
    for (int o = 16; o > 0; o >>= 1) ss += __shfl_xor_sync(0xffffffffu, ss, o);
    if ((tid & 31) == 0) red[tid >> 5] = ss;
    __syncthreads();
    if (tid < 8) {
        float sv = red[tid];
#pragma unroll
        for (int o = 4; o > 0; o >>= 1) sv += __shfl_xor_sync(0xffu, sv, o);
        if (tid == 0) red[0] = sv;
    }
    __syncthreads();
    float rms = rsqrtf(red[0] * (1.0f / (float)DM) + 1e-6f);
    float4 g = *(const float4*)&gamma[tid << 2];
    x.x *= rms * g.x; x.y *= rms * g.y; x.z *= rms * g.z; x.w *= rms * g.w;
    *(float4*)&out[(size_t)row * DM + (tid << 2)] = x;
}

// ---------------- launch ----------------
extern "C" void kernel_launch(void* const* d_in, const int* in_sizes, int n_in,
                              void* d_out, int out_size) {
    (void)in_sizes; (void)n_in; (void)out_size;
    const float* Q    = (const float*)d_in[0];
    const float* K    = (const float*)d_in[1];
    const float* V    = (const float*)d_in[2];
    const int*   mask = (const int*)d_in[3];
    const float* wq   = (const float*)d_in[4];
    const float* bq   = (const float*)d_in[5];
    const float* wk   = (const float*)d_in[6];
    const float* bk   = (const float*)d_in[7];
    const float* wv   = (const float*)d_in[8];
    const float* bv   = (const float*)d_in[9];
    const float* wo   = (const float*)d_in[10];
    const float* bo   = (const float*)d_in[11];
    const float* wnq  = (const float*)d_in[12];
    const float* bnq  = (const float*)d_in[13];
    const float* wnk  = (const float*)d_in[14];
    const float* bnk  = (const float*)d_in[15];
    const float* temp = (const float*)d_in[16];
    const float* gamma= (const float*)d_in[17];
    float* out = (float*)d_out;

    float *WQP, *WKP, *BQP, *BKP, *QFp, *KFp, *VPp, *CTXp;
    cudaGetSymbolAddress((void**)&WQP, g_WQP);
    cudaGetSymbolAddress((void**)&WKP, g_WKP);
    cudaGetSymbolAddress((void**)&BQP, g_BQP);
    cudaGetSymbolAddress((void**)&BKP, g_BKP);
    cudaGetSymbolAddress((void**)&QFp, g_QF);
    cudaGetSymbolAddress((void**)&KFp, g_KF);
    cudaGetSymbolAddress((void**)&VPp, g_VP);
    cudaGetSymbolAddress((void**)&CTXp, g_CTX);

    cudaFuncSetAttribute(flash_tc, cudaFuncAttributeMaxDynamicSharedMemorySize, FLASH_SMEM);

    fold_weights<<<DM * DM / 256, 256>>>(wq, bq, wnq, bnq, WQP, BQP);
    fold_weights<<<DM * DM / 256, 256>>>(wk, bk, wnk, bnk, WKP, BKP);

    dim3 ggrid(DM / GBN, NTOK / GBM);
    gemm_tc<<<ggrid, 256>>>(Q, WQP, BQP, QFp, 1);
    gemm_tc<<<ggrid, 256>>>(K, WKP, BKP, KFp, 1);
    gemm_tc<<<ggrid, 256>>>(V, wv, bv, VPp, 2);

    dim3 agrid(SEQ / 64, NH, 2);
    flash_tc<<<agrid, 128, FLASH_SMEM>>>(QFp, KFp, VPp, mask, temp, CTXp);

    gemm_tc<<<ggrid, 256>>>(CTXp, wo, bo, out, 0);
    rmsnorm_kernel<<<NTOK, 256>>>(out, gamma);
}

// round 3
// speedup vs baseline: 2.7376x; 1.3420x over previous
#include <cuda_runtime.h>
#include <math.h>

#define DM 1024
#define NH 16
#define DK 64
#define SEQ 2048
#define NTOK 4096   // B * SEQ

// ---------------- scratch (device globals) ----------------
__device__ float g_WQP[DM * DM];
__device__ float g_WKP[DM * DM];
__device__ float g_WVR[DM * DM];
__device__ float g_WOR[DM * DM];
__device__ float g_BQP[DM];
__device__ float g_BKP[DM];
__device__ float g_QR[NTOK * DM];
__device__ float g_KR[NTOK * DM];
__device__ float g_VR[NTOK * DM];
__device__ float g_QF[NTOK * DM];
__device__ float g_KF[NTOK * DM];
__device__ float g_VP[NTOK * DM];
__device__ float g_CTX[NTOK * DM];

// ---------------- helpers ----------------
__device__ __forceinline__ float rna_tf32(float x) {
    unsigned u;
    asm("cvt.rna.tf32.f32 %0, %1;" : "=r"(u) : "f"(x));
    return __uint_as_float(u);
}

__device__ __forceinline__ void mma8(float* c, const unsigned* a, unsigned b0, unsigned b1) {
    asm volatile(
        "mma.sync.aligned.m16n8k8.row.col.f32.tf32.tf32.f32 "
        "{%0,%1,%2,%3},{%4,%5,%6,%7},{%8,%9},{%0,%1,%2,%3};"
        : "+f"(c[0]), "+f"(c[1]), "+f"(c[2]), "+f"(c[3])
        : "r"(a[0]), "r"(a[1]), "r"(a[2]), "r"(a[3]), "r"(b0), "r"(b1));
}

__device__ __forceinline__ void cp16(float* dst_smem, const float* src) {
    unsigned s = (unsigned)__cvta_generic_to_shared(dst_smem);
    asm volatile("cp.async.cg.shared.global [%0], [%1], 16;\n" :: "r"(s), "l"(src));
}
__device__ __forceinline__ void cp_commit() {
    asm volatile("cp.async.commit_group;\n");
}
template <int N>
__device__ __forceinline__ void cp_wait() {
    asm volatile("cp.async.wait_group %0;\n" :: "n"(N));
}

// ---------------- prepass: tf32-round a tensor (float4-granular) ----------------
__global__ void round_copy(const float* __restrict__ src, float* __restrict__ dst) {
    int i = (blockIdx.x * blockDim.x + threadIdx.x) << 2;
    float4 v = *(const float4*)&src[i];
    v.x = rna_tf32(v.x); v.y = rna_tf32(v.y);
    v.z = rna_tf32(v.z); v.w = rna_tf32(v.w);
    *(float4*)&dst[i] = v;
}

// ---------------- fold per-head feature-map weights into projection ----------------
__global__ void fold_weights(const float* __restrict__ w, const float* __restrict__ b,
                             const float* __restrict__ wn, const float* __restrict__ bn,
                             float* __restrict__ wout, float* __restrict__ bout) {
    int idx = blockIdx.x * blockDim.x + threadIdx.x;
    if (idx >= DM * DM) return;
    int i = idx >> 10;
    int j = idx & 1023;
    int h = j >> 6, jj = j & 63;
    const float* wrow = w + i * DM + h * DK;
    float acc = 0.f;
#pragma unroll 8
    for (int d = 0; d < DK; d++) acc += wrow[d] * wn[d * DK + jj];
    wout[idx] = rna_tf32(acc);
    if (i == 0) {
        float bb = bn[jj];
        for (int d = 0; d < DK; d++) bb += b[h * DK + d] * wn[d * DK + jj];
        bout[j] = bb;
    }
}

// ---------------- tf32 TC GEMM, cp.async double-buffered ----------------
// BM=128 BN=128 BK=32; 256 thr / 8 warps (2x4); warp tile 64x32.
// As[m][k] stride 36 (4g+tig banks), Bs[k][n] stride 136.
#define GBM 128
#define GBN 128
#define GBK 32
#define GAS 36
#define GBS 136
#define GEMM_SMEM ((2 * GBM * GAS + 2 * GBK * GBS) * 4)

__global__ void __launch_bounds__(256) gemm_tc(
    const float* __restrict__ A, const float* __restrict__ W,
    const float* __restrict__ bias, float* __restrict__ C, int act) {
    extern __shared__ __align__(16) float sg[];
    float* As = sg;                       // [2][128][36]
    float* Bs = sg + 2 * GBM * GAS;       // [2][32][136]

    int tid = threadIdx.x;
    int warp = tid >> 5, lane = tid & 31;
    int g = lane >> 2, tig = lane & 3;
    int wm = warp >> 2, wn = warp & 3;
    int bm = blockIdx.y * GBM, bn = blockIdx.x * GBN;

    // loader coords (4 float4s each for A and B per thread)
    int ar[4], ak[4], bk[4], bn4[4];
#pragma unroll
    for (int i = 0; i < 4; i++) {
        int idx = tid + 256 * i;
        ar[i] = idx >> 3;  ak[i] = (idx & 7) << 2;
        bk[i] = idx >> 5;  bn4[i] = (idx & 31) << 2;
    }

    float acc[4][4][4];
#pragma unroll
    for (int m = 0; m < 4; m++)
#pragma unroll
        for (int j = 0; j < 4; j++)
#pragma unroll
            for (int t = 0; t < 4; t++) acc[m][j][t] = 0.f;

    // prologue: stage k0=0 into buf 0
#pragma unroll
    for (int i = 0; i < 4; i++) {
        cp16(&As[ar[i] * GAS + ak[i]], &A[(size_t)(bm + ar[i]) * DM + ak[i]]);
        cp16(&Bs[bk[i] * GBS + bn4[i]], &W[(size_t)bk[i] * DM + bn + bn4[i]]);
    }
    cp_commit();

    const int NK = DM / GBK;
    for (int kt = 0; kt < NK; kt++) {
        int buf = kt & 1;
        float* Ab = As + buf * GBM * GAS;
        float* Bb = Bs + buf * GBK * GBS;
        __syncthreads();   // all warps done computing on buf^1 -> safe to refill
        if (kt + 1 < NK) {
            int k0n = (kt + 1) * GBK;
            float* An = As + (buf ^ 1) * GBM * GAS;
            float* Bn = Bs + (buf ^ 1) * GBK * GBS;
#pragma unroll
            for (int i = 0; i < 4; i++) {
                cp16(&An[ar[i] * GAS + ak[i]], &A[(size_t)(bm + ar[i]) * DM + k0n + ak[i]]);
                cp16(&Bn[bk[i] * GBS + bn4[i]], &W[(size_t)(k0n + bk[i]) * DM + bn + bn4[i]]);
            }
            cp_commit();
            cp_wait<1>();
        } else {
            cp_wait<0>();
        }
        __syncthreads();

#pragma unroll
        for (int s = 0; s < 4; s++) {
            unsigned a[4][4], bb[4][2];
#pragma unroll
            for (int m = 0; m < 4; m++) {
                int m0 = wm * 64 + m * 16;
                a[m][0] = __float_as_uint(Ab[(m0 + g) * GAS + 8 * s + tig]);
                a[m][1] = __float_as_uint(Ab[(m0 + g + 8) * GAS + 8 * s + tig]);
                a[m][2] = __float_as_uint(Ab[(m0 + g) * GAS + 8 * s + tig + 4]);
                a[m][3] = __float_as_uint(Ab[(m0 + g + 8) * GAS + 8 * s + tig + 4]);
            }
#pragma unroll
            for (int j = 0; j < 4; j++) {
                int n0 = wn * 32 + j * 8;
                bb[j][0] = __float_as_uint(Bb[(8 * s + tig) * GBS + n0 + g]);
                bb[j][1] = __float_as_uint(Bb[(8 * s + tig + 4) * GBS + n0 + g]);
            }
#pragma unroll
            for (int m = 0; m < 4; m++)
#pragma unroll
                for (int j = 0; j < 4; j++)
                    mma8(acc[m][j], a[m], bb[j][0], bb[j][1]);
        }
    }

    // epilogue
#pragma unroll
    for (int m = 0; m < 4; m++) {
        int row0 = bm + wm * 64 + m * 16 + g;
#pragma unroll
        for (int j = 0; j < 4; j++) {
            int col = bn + wn * 32 + j * 8 + 2 * tig;
            float b0 = bias[col], b1 = bias[col + 1];
            float v0 = acc[m][j][0] + b0, v1 = acc[m][j][1] + b1;
            float v2 = acc[m][j][2] + b0, v3 = acc[m][j][3] + b1;
            if (act == 1) {
                v0 = rna_tf32(tanhf(v0)); v1 = rna_tf32(tanhf(v1));
                v2 = rna_tf32(tanhf(v2)); v3 = rna_tf32(tanhf(v3));
            } else if (act == 2) {
                v0 = rna_tf32(v0); v1 = rna_tf32(v1);
                v2 = rna_tf32(v2); v3 = rna_tf32(v3);
            }
            *(float2*)&C[(size_t)row0 * DM + col] = make_float2(v0, v1);
            *(float2*)&C[(size_t)(row0 + 8) * DM + col] = make_float2(v2, v3);
        }
    }
}

// ---------------- tensor-core flash attention, 128-q blocks ----------------
// 256 threads / 8 warps, each warp owns 16 q-rows. K/V 64-row tiles, cp.async x2 buf.
#define FQS 68
#define FVS 72
#define FBM 128
#define FLASH_SMEM ((FBM * FQS + 2 * 64 * FQS + 2 * 64 * FVS) * 4)

__global__ void __launch_bounds__(256) flash_tc(
    const float* __restrict__ QF, const float* __restrict__ KF,
    const float* __restrict__ V, const int* __restrict__ mask,
    const float* __restrict__ temp, float* __restrict__ CTX) {
    extern __shared__ __align__(16) float sm[];
    float* Qs = sm;                          // 128 x FQS (later aliased by Ps)
    float* Ks = sm + FBM * FQS;              // 2 x 64 x FQS
    float* Vs = Ks + 2 * 64 * FQS;           // 2 x 64 x FVS
    float* Ps = Qs;

    int tid = threadIdx.x;
    int warp = tid >> 5, lane = tid & 31;
    int g = lane >> 2, tig = lane & 3;
    int q0 = blockIdx.x * FBM, h = blockIdx.y, b = blockIdx.z;
    int r0 = warp * 16 + g;

    // load Q tile (tf32-rounded already)
#pragma unroll
    for (int i = 0; i < 8; i++) {
        int idx = tid + 256 * i;
        int r = idx >> 4, d4 = (idx & 15) << 2;
        *(float4*)&Qs[r * FQS + d4] =
            *(const float4*)&QF[(size_t)(b * SEQ + q0 + r) * DM + h * DK + d4];
    }
    __syncthreads();

    unsigned qa[8][4];
#pragma unroll
    for (int s = 0; s < 8; s++) {
        qa[s][0] = __float_as_uint(Qs[r0 * FQS + 8 * s + tig]);
        qa[s][1] = __float_as_uint(Qs[(r0 + 8) * FQS + 8 * s + tig]);
        qa[s][2] = __float_as_uint(Qs[r0 * FQS + 8 * s + tig + 4]);
        qa[s][3] = __float_as_uint(Qs[(r0 + 8) * FQS + 8 * s + tig + 4]);
    }

    // K/V loader coords: 4 float4 each per thread
    int lr[4], ld4[4];
#pragma unroll
    for (int i = 0; i < 4; i++) {
        int idx = tid + 256 * i;
        lr[i] = idx >> 4;  ld4[i] = (idx & 15) << 2;
    }

    float scale = 0.125f / temp[h];
    float mr0 = -1e30f, mr1 = -1e30f, l0 = 0.f, l1 = 0.f;
    float acc[8][4];
#pragma unroll
    for (int j = 0; j < 8; j++)
#pragma unroll
        for (int t = 0; t < 4; t++) acc[j][t] = 0.f;

    // prologue: stage kt=0
#pragma unroll
    for (int i = 0; i < 4; i++) {
        size_t src = (size_t)(b * SEQ + lr[i]) * DM + h * DK + ld4[i];
        cp16(&Ks[lr[i] * FQS + ld4[i]], &KF[src]);
        cp16(&Vs[lr[i] * FVS + ld4[i]], &V[src]);
    }
    cp_commit();

    const int NKT = SEQ / 64;
    for (int kt = 0; kt < NKT; kt++) {
        int buf = kt & 1;
        float* Kb = Ks + buf * 64 * FQS;
        float* Vb = Vs + buf * 64 * FVS;
        __syncthreads();   // all warps done with buf^1 of previous iteration
        if (kt + 1 < NKT) {
            float* Kn = Ks + (buf ^ 1) * 64 * FQS;
            float* Vn = Vs + (buf ^ 1) * 64 * FVS;
#pragma unroll
            for (int i = 0; i < 4; i++) {
                size_t src = (size_t)(b * SEQ + (kt + 1) * 64 + lr[i]) * DM + h * DK + ld4[i];
                cp16(&Kn[lr[i] * FQS + ld4[i]], &KF[src]);
                cp16(&Vn[lr[i] * FVS + ld4[i]], &V[src]);
            }
            cp_commit();
            cp_wait<1>();
        } else {
            cp_wait<0>();
        }
        __syncthreads();

        // S = Qf @ Kf^T
        float sD[8][4];
#pragma unroll
        for (int j = 0; j < 8; j++)
#pragma unroll
            for (int t = 0; t < 4; t++) sD[j][t] = 0.f;
#pragma unroll
        for (int s = 0; s < 8; s++)
#pragma unroll
            for (int j = 0; j < 8; j++) {
                unsigned b0 = __float_as_uint(Kb[(8 * j + g) * FQS + 8 * s + tig]);
                unsigned b1 = __float_as_uint(Kb[(8 * j + g) * FQS + 8 * s + tig + 4]);
                mma8(sD[j], qa[s], b0, b1);
            }

        // scale + mask
#pragma unroll
        for (int j = 0; j < 8; j++) {
            int c = kt * 64 + 8 * j + 2 * tig;
            int2 mA = *(const int2*)&mask[(size_t)(q0 + r0) * SEQ + c];
            int2 mB = *(const int2*)&mask[(size_t)(q0 + r0 + 8) * SEQ + c];
            sD[j][0] = mA.x ? sD[j][0] * scale : -1e9f;
            sD[j][1] = mA.y ? sD[j][1] * scale : -1e9f;
            sD[j][2] = mB.x ? sD[j][2] * scale : -1e9f;
            sD[j][3] = mB.y ? sD[j][3] * scale : -1e9f;
        }

        // online softmax (rows r0 and r0+8; reduce over quad lanes)
        float mx0 = -1e30f, mx1 = -1e30f;
#pragma unroll
        for (int j = 0; j < 8; j++) {
            mx0 = fmaxf(mx0, fmaxf(sD[j][0], sD[j][1]));
            mx1 = fmaxf(mx1, fmaxf(sD[j][2], sD[j][3]));
        }
        mx0 = fmaxf(mx0, __shfl_xor_sync(0xffffffffu, mx0, 1));
        mx0 = fmaxf(mx0, __shfl_xor_sync(0xffffffffu, mx0, 2));
        mx1 = fmaxf(mx1, __shfl_xor_sync(0xffffffffu, mx1, 1));
        mx1 = fmaxf(mx1, __shfl_xor_sync(0xffffffffu, mx1, 2));
        float nm0 = fmaxf(mr0, mx0), nm1 = fmaxf(mr1, mx1);
        float corr0 = __expf(mr0 - nm0), corr1 = __expf(mr1 - nm1);
        mr0 = nm0; mr1 = nm1;

        float s0 = 0.f, s1 = 0.f;
#pragma unroll
        for (int j = 0; j < 8; j++) {
            float p0 = __expf(sD[j][0] - nm0);
            float p1 = __expf(sD[j][1] - nm0);
            float p2 = __expf(sD[j][2] - nm1);
            float p3 = __expf(sD[j][3] - nm1);
            s0 += p0 + p1; s1 += p2 + p3;
            *(float2*)&Ps[r0 * FQS + 8 * j + 2 * tig] =
                make_float2(rna_tf32(p0), rna_tf32(p1));
            *(float2*)&Ps[(r0 + 8) * FQS + 8 * j + 2 * tig] =
                make_float2(rna_tf32(p2), rna_tf32(p3));
        }
        s0 += __shfl_xor_sync(0xffffffffu, s0, 1);
        s0 += __shfl_xor_sync(0xffffffffu, s0, 2);
        s1 += __shfl_xor_sync(0xffffffffu, s1, 1);
        s1 += __shfl_xor_sync(0xffffffffu, s1, 2);
        l0 = l0 * corr0 + s0;
        l1 = l1 * corr1 + s1;
#pragma unroll
        for (int j = 0; j < 8; j++) {
            acc[j][0] *= corr0; acc[j][1] *= corr0;
            acc[j][2] *= corr1; acc[j][3] *= corr1;
        }
        __syncwarp();   // Ps rows produced & consumed within the same warp

        // ctx += P @ V
#pragma unroll
        for (int s = 0; s < 8; s++) {
            unsigned pa[4];
            pa[0] = __float_as_uint(Ps[r0 * FQS + 8 * s + tig]);
            pa[1] = __float_as_uint(Ps[(r0 + 8) * FQS + 8 * s + tig]);
            pa[2] = __float_as_uint(Ps[r0 * FQS + 8 * s + tig + 4]);
            pa[3] = __float_as_uint(Ps[(r0 + 8) * FQS + 8 * s + tig + 4]);
#pragma unroll
            for (int j = 0; j < 8; j++) {
                unsigned b0 = __float_as_uint(Vb[(8 * s + tig) * FVS + 8 * j + g]);
                unsigned b1 = __float_as_uint(Vb[(8 * s + tig + 4) * FVS + 8 * j + g]);
                mma8(acc[j], pa, b0, b1);
            }
        }
    }

    // epilogue (tf32-round: CTX feeds out-proj GEMM A operand)
    float inv0 = 1.0f / l0, inv1 = 1.0f / l1;
#pragma unroll
    for (int j = 0; j < 8; j++) {
        int col = h * DK + 8 * j + 2 * tig;
        *(float2*)&CTX[(size_t)(b * SEQ + q0 + r0) * DM + col] =
            make_float2(rna_tf32(acc[j][0] * inv0), rna_tf32(acc[j][1] * inv0));
        *(float2*)&CTX[(size_t)(b * SEQ + q0 + r0 + 8) * DM + col] =
            make_float2(rna_tf32(acc[j][2] * inv1), rna_tf32(acc[j][3] * inv1));
    }
}

// ---------------- in-place RMSNorm ----------------
__global__ void __launch_bounds__(256) rmsnorm_kernel(float* __restrict__ out,
                                                      const float* __restrict__ gamma) {
    int row = blockIdx.x;
    int tid = threadIdx.x;
    float4 x = *(const float4*)&out[(size_t)row * DM + (tid << 2)];
    float ss = x.x * x.x + x.y * x.y + x.z * x.z + x.w * x.w;
    __shared__ float red[8];
#pragma unroll
    for (int o = 16; o > 0; o >>= 1) ss += __shfl_xor_sync(0xffffffffu, ss, o);
    if ((tid & 31) == 0) red[tid >> 5] = ss;
    __syncthreads();
    if (tid < 8) {
        float sv = red[tid];
#pragma unroll
        for (int o = 4; o > 0; o >>= 1) sv += __shfl_xor_sync(0xffu, sv, o);
        if (tid == 0) red[0] = sv;
    }
    __syncthreads();
    float rms = rsqrtf(red[0] * (1.0f / (float)DM) + 1e-6f);
    float4 g = *(const float4*)&gamma[tid << 2];
    x.x *= rms * g.x; x.y *= rms * g.y; x.z *= rms * g.z; x.w *= rms * g.w;
    *(float4*)&out[(size_t)row * DM + (tid << 2)] = x;
}

// ---------------- launch ----------------
extern "C" void kernel_launch(void* const* d_in, const int* in_sizes, int n_in,
                              void* d_out, int out_size) {
    (void)in_sizes; (void)n_in; (void)out_size;
    const float* Q    = (const float*)d_in[0];
    const float* K    = (const float*)d_in[1];
    const float* V    = (const float*)d_in[2];
    const int*   mask = (const int*)d_in[3];
    const float* wq   = (const float*)d_in[4];
    const float* bq   = (const float*)d_in[5];
    const float* wk   = (const float*)d_in[6];
    const float* bk   = (const float*)d_in[7];
    const float* wv   = (const float*)d_in[8];
    const float* bv   = (const float*)d_in[9];
    const float* wo   = (const float*)d_in[10];
    const float* bo   = (const float*)d_in[11];
    const float* wnq  = (const float*)d_in[12];
    const float* bnq  = (const float*)d_in[13];
    const float* wnk  = (const float*)d_in[14];
    const float* bnk  = (const float*)d_in[15];
    const float* temp = (const float*)d_in[16];
    const float* gamma= (const float*)d_in[17];
    float* out = (float*)d_out;

    float *WQP, *WKP, *WVR, *WOR, *BQP, *BKP, *QR, *KR, *VR, *QFp, *KFp, *VPp, *CTXp;
    cudaGetSymbolAddress((void**)&WQP, g_WQP);
    cudaGetSymbolAddress((void**)&WKP, g_WKP);
    cudaGetSymbolAddress((void**)&WVR, g_WVR);
    cudaGetSymbolAddress((void**)&WOR, g_WOR);
    cudaGetSymbolAddress((void**)&BQP, g_BQP);
    cudaGetSymbolAddress((void**)&BKP, g_BKP);
    cudaGetSymbolAddress((void**)&QR, g_QR);
    cudaGetSymbolAddress((void**)&KR, g_KR);
    cudaGetSymbolAddress((void**)&VR, g_VR);
    cudaGetSymbolAddress((void**)&QFp, g_QF);
    cudaGetSymbolAddress((void**)&KFp, g_KF);
    cudaGetSymbolAddress((void**)&VPp, g_VP);
    cudaGetSymbolAddress((void**)&CTXp, g_CTX);

    cudaFuncSetAttribute(gemm_tc, cudaFuncAttributeMaxDynamicSharedMemorySize, GEMM_SMEM);
    cudaFuncSetAttribute(flash_tc, cudaFuncAttributeMaxDynamicSharedMemorySize, FLASH_SMEM);

    // prepass: tf32-round GEMM A/W operands
    round_copy<<<NTOK * DM / 1024, 256>>>(Q, QR);
    round_copy<<<NTOK * DM / 1024, 256>>>(K, KR);
    round_copy<<<NTOK * DM / 1024, 256>>>(V, VR);
    round_copy<<<DM * DM / 1024, 256>>>(wv, WVR);
    round_copy<<<DM * DM / 1024, 256>>>(wo, WOR);

    fold_weights<<<DM * DM / 256, 256>>>(wq, bq, wnq, bnq, WQP, BQP);
    fold_weights<<<DM * DM / 256, 256>>>(wk, bk, wnk, bnk, WKP, BKP);

    dim3 ggrid(DM / GBN, NTOK / GBM);
    gemm_tc<<<ggrid, 256, GEMM_SMEM>>>(QR, WQP, BQP, QFp, 1);
    gemm_tc<<<ggrid, 256, GEMM_SMEM>>>(KR, WKP, BKP, KFp, 1);
    gemm_tc<<<ggrid, 256, GEMM_SMEM>>>(VR, WVR, bv, VPp, 2);

    dim3 agrid(SEQ / FBM, NH, 2);
    flash_tc<<<agrid, 256, FLASH_SMEM>>>(QFp, KFp, VPp, mask, temp, CTXp);

    gemm_tc<<<ggrid, 256, GEMM_SMEM>>>(CTXp, WOR, bo, out, 0);
    rmsnorm_kernel<<<NTOK, 256>>>(out, gamma);
}